// round 7
// baseline (speedup 1.0000x reference)
#include <cuda_runtime.h>

#define N_EMIT 512
#define ZPL    8
#define ROI    20
#define NPX    400
#define SPL_D  64
#define SPL_H  40
#define SPL_W  40
#define TPITCH 33

typedef unsigned long long u64;

__device__ __forceinline__ u64 ffma2(u64 a, u64 b, u64 c) {
    u64 d;
    asm("fma.rn.f32x2 %0, %1, %2, %3;" : "=l"(d) : "l"(a), "l"(b), "l"(c));
    return d;
}
__device__ __forceinline__ u64 fmul2(u64 a, u64 b) {
    u64 d;
    asm("mul.rn.f32x2 %0, %1, %2;" : "=l"(d) : "l"(a), "l"(b));
    return d;
}
__device__ __forceinline__ u64 fpack2(float lo, float hi) {
    u64 d;
    asm("mov.b64 %0, {%1, %2};" : "=l"(d) : "f"(lo), "f"(hi));
    return d;
}
__device__ __forceinline__ float fhadd2(u64 a) {
    float lo, hi;
    asm("mov.b64 {%0, %1}, %2;" : "=f"(lo), "=f"(hi) : "l"(a));
    return lo + hi;
}

// One block = (echunk of 32 emitters) x (one z plane). 1024 threads = 32 warps.
// lane = emitter; warp w owns 13 (w<16) or 12 (w>=16) pixels.
__global__ __launch_bounds__(1024, 1) void psf_fused(
    const float* __restrict__ pos,
    const float* __restrict__ inten,
    const float* __restrict__ bg,
    const float* __restrict__ coefs,
    float* __restrict__ out)
{
    extern __shared__ float sval[];          // [NPX * TPITCH] transpose tile
    __shared__ float ssum[32][TPITCH];

    const int echunk = blockIdx.x & 15;
    const int z      = blockIdx.x >> 4;
    const int w      = threadIdx.x >> 5;
    const int lane   = threadIdx.x & 31;
    const int e      = echunk * 32 + lane;

    const float p0 = pos[e * 3 + 0];   // Y axis (faithful to reference)
    const float p1 = pos[e * 3 + 1];   // X axis
    const float p2 = pos[e * 3 + 2];   // Z axis

    // z terms (exact, constant per block)
    float pzf = (float)z - p2 + 28.0f;            // SPL_D/2 - ZPL/2
    float fz  = floorf(pzf);
    float dz  = pzf - fz;
    int   iz  = max(0, min((int)fz, SPL_D - 1));
    float dz2 = dz * dz, dz3 = dz2 * dz;
    const int izoff = iz * SPL_H;

    // Base fractional parts / indices at y=0, x=0 (exact reference expressions)
    float py0 = (0.0f - p0) + 10.0f;
    float fy0 = floorf(py0);
    float dy  = py0 - fy0;
    int   iy0 = (int)fy0;

    float px0 = (0.0f - p1) + 10.0f;
    float fx0 = floorf(px0);
    float dx  = px0 - fx0;
    int   ix0 = (int)fx0;

    // Genericity check: every row/col floor must follow the linear pattern,
    // and no clamping may trigger.
    bool ok = (iy0 >= 0) && (iy0 + ROI - 1 < SPL_H) &&
              (ix0 >= 0) && (ix0 + ROI - 1 < SPL_W);
    #pragma unroll
    for (int q = 1; q < ROI; q++) {
        ok &= floorf(((float)q - p0) + 10.0f) == (float)(iy0 + q);
        ok &= floorf(((float)q - p1) + 10.0f) == (float)(ix0 + q);
    }

    const int cnt    = (w < 16) ? 13 : 12;
    const int pstart = (w < 16) ? w * 13 : 208 + (w - 16) * 12;

    float nsum = 0.0f;

    if (!__syncthreads_or(!ok)) {
        // ---------------- FAST PATH (generic, basis constant per lane) ------
        float dx2 = dx * dx, dx3 = dx2 * dx;
        float dy2 = dy * dy, dy3 = dy2 * dy;

        const u64 q01 = fpack2(1.0f, dx);
        const u64 q23 = fpack2(dx2, dx3);

        // By[b][0] = (wy_b, wy_b*dx), By[b][1] = (wy_b*dx2, wy_b*dx3)
        u64 By[4][2];
        By[0][0] = q01;                 By[0][1] = q23;
        u64 wp1 = fpack2(dy,  dy );     By[1][0] = fmul2(q01, wp1); By[1][1] = fmul2(q23, wp1);
        u64 wp2 = fpack2(dy2, dy2);     By[2][0] = fmul2(q01, wp2); By[2][1] = fmul2(q23, wp2);
        u64 wp3 = fpack2(dy3, dy3);     By[3][0] = fmul2(q01, wp3); By[3][1] = fmul2(q23, wp3);

        const float* base = coefs + (((size_t)(izoff + iy0) * SPL_W + ix0) << 6);

        #pragma unroll
        for (int i = 0; i < 13; i++) {
            if (i < cnt) {
                const int p = pstart + i;
                const int y = p / 20;
                const int x = p - y * 20;

                const ulonglong2* cp = (const ulonglong2*)(base + ((y * SPL_W + x) << 6));

                u64 acc0 = 0ULL, acc1 = 0ULL, acc2 = 0ULL, acc3 = 0ULL;
                #pragma unroll
                for (int bq = 0; bq < 4; bq++) {
                    ulonglong2 v0 = cp[0 * 4 + bq];
                    ulonglong2 v1 = cp[1 * 4 + bq];
                    ulonglong2 v2 = cp[2 * 4 + bq];
                    ulonglong2 v3 = cp[3 * 4 + bq];
                    acc0 = ffma2(v0.x, By[bq][0], acc0);
                    acc0 = ffma2(v0.y, By[bq][1], acc0);
                    acc1 = ffma2(v1.x, By[bq][0], acc1);
                    acc1 = ffma2(v1.y, By[bq][1], acc1);
                    acc2 = ffma2(v2.x, By[bq][0], acc2);
                    acc2 = ffma2(v2.y, By[bq][1], acc2);
                    acc3 = ffma2(v3.x, By[bq][0], acc3);
                    acc3 = ffma2(v3.y, By[bq][1], acc3);
                }
                float s0 = fhadd2(acc0);
                float s1 = fhadd2(acc1);
                float s2 = fhadd2(acc2);
                float s3 = fhadd2(acc3);
                float v  = fmaf(s3, dz3, fmaf(s2, dz2, fmaf(s1, dz, s0)));

                sval[p * TPITCH + lane] = v;
                nsum += v;
            }
        }
    } else {
        // ---------------- EXACT FALLBACK (bit-faithful per pixel) -----------
        #pragma unroll 2
        for (int i = 0; i < 13; i++) {
            if (i < cnt) {
                const int p = pstart + i;
                const int y = p / 20;
                const int x = p - y * 20;

                float pyf = (float)y - p0 + 10.0f;
                float fy  = floorf(pyf);
                float dyy = pyf - fy;
                int   iy  = max(0, min((int)fy, SPL_H - 1));

                float pxf = (float)x - p1 + 10.0f;
                float fx  = floorf(pxf);
                float dxx = pxf - fx;
                int   ix  = max(0, min((int)fx, SPL_W - 1));

                float dxx2 = dxx * dxx, dxx3 = dxx2 * dxx;
                float dyy2 = dyy * dyy, dyy3 = dyy2 * dyy;

                const float4* cp = (const float4*)(coefs +
                    (((size_t)(izoff + iy) * SPL_W + ix) << 6));

                float s[4];
                #pragma unroll
                for (int a = 0; a < 4; a++) {
                    float4 c0 = cp[a * 4 + 0];
                    float4 c1 = cp[a * 4 + 1];
                    float4 c2 = cp[a * 4 + 2];
                    float4 c3 = cp[a * 4 + 3];
                    float t0 = fmaf(c0.w, dxx3, fmaf(c0.z, dxx2, fmaf(c0.y, dxx, c0.x)));
                    float t1 = fmaf(c1.w, dxx3, fmaf(c1.z, dxx2, fmaf(c1.y, dxx, c1.x)));
                    float t2 = fmaf(c2.w, dxx3, fmaf(c2.z, dxx2, fmaf(c2.y, dxx, c2.x)));
                    float t3 = fmaf(c3.w, dxx3, fmaf(c3.z, dxx2, fmaf(c3.y, dxx, c3.x)));
                    s[a] = fmaf(t3, dyy3, fmaf(t2, dyy2, fmaf(t1, dyy, t0)));
                }
                float v = fmaf(s[3], dz3, fmaf(s[2], dz2, fmaf(s[1], dz, s[0])));

                sval[p * TPITCH + lane] = v;
                nsum += v;
            }
        }
    }

    // Per-emitter plane sums
    ssum[w][lane] = nsum;
    __syncthreads();

    // Warp w handles emitter w: transposed read + butterfly reduce
    float t = ssum[lane][w];
    #pragma unroll
    for (int off = 16; off > 0; off >>= 1)
        t += __shfl_xor_sync(0xffffffffu, t, off);

    const int   eo  = echunk * 32 + w;
    const float sc  = inten[eo * ZPL + z] / t;
    const float bgv = bg[eo * ZPL + z];
    float* op = out + ((size_t)eo * ZPL + z) * NPX;

    #pragma unroll
    for (int m = 0; m < 13; m++) {
        int pp = m * 32 + lane;
        if (pp < NPX) op[pp] = fmaf(sval[pp * TPITCH + w], sc, bgv);
    }
}

extern "C" void kernel_launch(void* const* d_in, const int* in_sizes, int n_in,
                              void* d_out, int out_size)
{
    const float* pos   = (const float*)d_in[0];
    const float* inten = (const float*)d_in[1];
    const float* bg    = (const float*)d_in[2];
    const float* coefs = (const float*)d_in[3];

    const int smem = NPX * TPITCH * sizeof(float);   // 52.8 KB dynamic
    cudaFuncSetAttribute(psf_fused, cudaFuncAttributeMaxDynamicSharedMemorySize, smem);
    psf_fused<<<128, 1024, smem>>>(pos, inten, bg, coefs, (float*)d_out);
}

// round 8
// speedup vs baseline: 1.4943x; 1.4943x over previous
#include <cuda_runtime.h>

#define N_EMIT 512
#define ZPL    8
#define ROI    20
#define NPX    400
#define SPL_D  64
#define SPL_H  40
#define SPL_W  40
#define TPITCH 33

// Dynamic smem: [25600] staged coefs (400 cells x 64f), then [NPX*TPITCH] transpose tile.
#define STAGE_F4 6400            // 400 cells * 16 float4

// One block = (echunk of 32 emitters) x (one z plane). 1024 threads = 32 warps.
// lane = emitter; warp w owns 13 (w<16) or 12 (w>=16) pixels.
__global__ __launch_bounds__(1024, 1) void psf_fused(
    const float* __restrict__ pos,
    const float* __restrict__ inten,
    const float* __restrict__ bg,
    const float* __restrict__ coefs,
    float* __restrict__ out)
{
    extern __shared__ float dyn[];
    float* sstage = dyn;                  // 25600 floats
    float* sval   = dyn + 25600;          // NPX * TPITCH
    __shared__ float ssum[32][TPITCH];

    const int echunk = blockIdx.x & 15;
    const int z      = blockIdx.x >> 4;
    const int w      = threadIdx.x >> 5;
    const int lane   = threadIdx.x & 31;
    const int e      = echunk * 32 + lane;

    const float p0 = pos[e * 3 + 0];   // Y axis (faithful to reference)
    const float p1 = pos[e * 3 + 1];   // X axis
    const float p2 = pos[e * 3 + 2];   // Z axis

    // z terms (exact reference expressions)
    float pzf = (float)z - p2 + 28.0f;            // SPL_D/2 - ZPL/2
    float fz  = floorf(pzf);
    float dz  = pzf - fz;
    int   iz  = max(0, min((int)fz, SPL_D - 1));
    const int izoff = iz * SPL_H;

    // Base fractional parts / indices at y=0, x=0
    float py0 = (0.0f - p0) + 10.0f;              // SPL_H/2 - ROI/2
    float fy0 = floorf(py0);
    float dy  = py0 - fy0;
    int   iy0 = (int)fy0;

    float px0 = (0.0f - p1) + 10.0f;              // SPL_W/2 - ROI/2
    float fx0 = floorf(px0);
    float dx  = px0 - fx0;
    int   ix0 = (int)fx0;

    // Genericity: all lanes must hit the canonical translated grid, and every
    // row/col floor must follow the +1 pattern (catches ulp edge cases).
    bool ok = (iy0 == 9) && (ix0 == 9) && (iz == z + 27);
    #pragma unroll
    for (int q = 1; q < ROI; q++) {
        ok &= floorf(((float)q - p0) + 10.0f) == (float)(iy0 + q);
        ok &= floorf(((float)q - p1) + 10.0f) == (float)(ix0 + q);
    }

    const int  cnt    = (w < 16) ? 13 : 12;
    const int  pstart = (w < 16) ? w * 13 : 208 + (w - 16) * 12;
    const bool fast   = !__syncthreads_or(!ok);

    float dz2 = dz * dz, dz3 = dz2 * dz;
    float nsum = 0.0f;

    if (fast) {
        // ---- Stage 400 cells (100 KB) compactly: cell p -> sstage + p*64 ----
        {
            const float4* src4 = (const float4*)(coefs +
                ((((size_t)(z + 27) * SPL_H + 9) * SPL_W + 9) << 6));
            float4* dst4 = (float4*)sstage;
            #pragma unroll
            for (int k = 0; k < 7; k++) {
                int i = threadIdx.x + k * 1024;
                if (i < STAGE_F4) {
                    int y = i / 320;              // 20 cells * 16 f4 per row
                    int c = i - y * 320;
                    dst4[i] = src4[y * 640 + c];  // global row = 40 cells = 640 f4
                }
            }
        }

        // Per-thread constant weights w[a*4+b] = dz^a * dy^b
        float dx2 = dx * dx, dx3 = dx2 * dx;
        float dy2 = dy * dy, dy3 = dy2 * dy;
        float wab[16];
        {
            float zp[4] = {1.0f, dz, dz2, dz3};
            float yp[4] = {1.0f, dy, dy2, dy3};
            #pragma unroll
            for (int a = 0; a < 4; a++)
                #pragma unroll
                for (int bq = 0; bq < 4; bq++)
                    wab[a * 4 + bq] = zp[a] * yp[bq];
        }
        __syncthreads();

        #pragma unroll
        for (int i = 0; i < 13; i++) {
            if (i < cnt) {
                const int p = pstart + i;
                const float4* cp = (const float4*)sstage + (p << 4);

                float acc[4] = {0.0f, 0.0f, 0.0f, 0.0f};
                #pragma unroll
                for (int t = 0; t < 16; t++) {
                    float4 c = cp[t];             // LDS.128 broadcast (free)
                    float  d = fmaf(c.w, dx3, fmaf(c.z, dx2, fmaf(c.y, dx, c.x)));
                    acc[t & 3] = fmaf(d, wab[t], acc[t & 3]);
                }
                float v = (acc[0] + acc[1]) + (acc[2] + acc[3]);

                sval[p * TPITCH + lane] = v;
                nsum += v;
            }
        }
    } else {
        // ---------------- EXACT FALLBACK (bit-faithful per pixel) -----------
        #pragma unroll 2
        for (int i = 0; i < 13; i++) {
            if (i < cnt) {
                const int p = pstart + i;
                const int y = p / 20;
                const int x = p - y * 20;

                float pyf = (float)y - p0 + 10.0f;
                float fy  = floorf(pyf);
                float dyy = pyf - fy;
                int   iy  = max(0, min((int)fy, SPL_H - 1));

                float pxf = (float)x - p1 + 10.0f;
                float fx  = floorf(pxf);
                float dxx = pxf - fx;
                int   ix  = max(0, min((int)fx, SPL_W - 1));

                float dxx2 = dxx * dxx, dxx3 = dxx2 * dxx;
                float dyy2 = dyy * dyy, dyy3 = dyy2 * dyy;

                const float4* cp = (const float4*)(coefs +
                    (((size_t)(izoff + iy) * SPL_W + ix) << 6));

                float s[4];
                #pragma unroll
                for (int a = 0; a < 4; a++) {
                    float4 c0 = cp[a * 4 + 0];
                    float4 c1 = cp[a * 4 + 1];
                    float4 c2 = cp[a * 4 + 2];
                    float4 c3 = cp[a * 4 + 3];
                    float t0 = fmaf(c0.w, dxx3, fmaf(c0.z, dxx2, fmaf(c0.y, dxx, c0.x)));
                    float t1 = fmaf(c1.w, dxx3, fmaf(c1.z, dxx2, fmaf(c1.y, dxx, c1.x)));
                    float t2 = fmaf(c2.w, dxx3, fmaf(c2.z, dxx2, fmaf(c2.y, dxx, c2.x)));
                    float t3 = fmaf(c3.w, dxx3, fmaf(c3.z, dxx2, fmaf(c3.y, dxx, c3.x)));
                    s[a] = fmaf(t3, dyy3, fmaf(t2, dyy2, fmaf(t1, dyy, t0)));
                }
                float v = fmaf(s[3], dz3, fmaf(s[2], dz2, fmaf(s[1], dz, s[0])));

                sval[p * TPITCH + lane] = v;
                nsum += v;
            }
        }
    }

    // Per-emitter plane sums
    ssum[w][lane] = nsum;
    __syncthreads();

    // Warp w handles emitter w: transposed read + butterfly reduce
    float t = ssum[lane][w];
    #pragma unroll
    for (int off = 16; off > 0; off >>= 1)
        t += __shfl_xor_sync(0xffffffffu, t, off);

    const int   eo  = echunk * 32 + w;
    const float sc  = inten[eo * ZPL + z] / t;
    const float bgv = bg[eo * ZPL + z];
    float* op = out + ((size_t)eo * ZPL + z) * NPX;

    #pragma unroll
    for (int m = 0; m < 13; m++) {
        int pp = m * 32 + lane;
        if (pp < NPX) op[pp] = fmaf(sval[pp * TPITCH + w], sc, bgv);
    }
}

extern "C" void kernel_launch(void* const* d_in, const int* in_sizes, int n_in,
                              void* d_out, int out_size)
{
    const float* pos   = (const float*)d_in[0];
    const float* inten = (const float*)d_in[1];
    const float* bg    = (const float*)d_in[2];
    const float* coefs = (const float*)d_in[3];

    const int smem = (25600 + NPX * TPITCH) * sizeof(float);   // ~154 KB dynamic
    cudaFuncSetAttribute(psf_fused, cudaFuncAttributeMaxDynamicSharedMemorySize, smem);
    psf_fused<<<128, 1024, smem>>>(pos, inten, bg, coefs, (float*)d_out);
}

// round 9
// speedup vs baseline: 1.5057x; 1.0076x over previous
#include <cuda_runtime.h>

#define N_EMIT 512
#define ZPL    8
#define ROI    20
#define NPX    400
#define SPL_D  64
#define SPL_H  40
#define SPL_W  40
#define TPITCH 33
#define STAGE_F4 6400            // 400 cells * 16 float4

typedef unsigned long long u64;

__device__ __forceinline__ u64 ffma2(u64 a, u64 b, u64 c) {
    u64 d;
    asm("fma.rn.f32x2 %0, %1, %2, %3;" : "=l"(d) : "l"(a), "l"(b), "l"(c));
    return d;
}
__device__ __forceinline__ u64 fmul2(u64 a, u64 b) {
    u64 d;
    asm("mul.rn.f32x2 %0, %1, %2;" : "=l"(d) : "l"(a), "l"(b));
    return d;
}
__device__ __forceinline__ u64 fpack2(float lo, float hi) {
    u64 d;
    asm("mov.b64 %0, {%1, %2};" : "=l"(d) : "f"(lo), "f"(hi));
    return d;
}
__device__ __forceinline__ float fhadd2(u64 a) {
    float lo, hi;
    asm("mov.b64 {%0, %1}, %2;" : "=f"(lo), "=f"(hi) : "l"(a));
    return lo + hi;
}

// One block = (echunk of 32 emitters) x (one z plane). 1024 threads = 32 warps.
// lane = emitter; warp w owns 13 (w<16) or 12 (w>=16) pixels.
__global__ __launch_bounds__(1024, 1) void psf_fused(
    const float* __restrict__ pos,
    const float* __restrict__ inten,
    const float* __restrict__ bg,
    const float* __restrict__ coefs,
    float* __restrict__ out)
{
    extern __shared__ float dyn[];
    float* sstage = dyn;                  // 25600 floats (400 cells x 64)
    float* sval   = dyn + 25600;          // NPX * TPITCH
    __shared__ float ssum[32][TPITCH];

    const int echunk = blockIdx.x & 15;
    const int z      = blockIdx.x >> 4;
    const int w      = threadIdx.x >> 5;
    const int lane   = threadIdx.x & 31;
    const int e      = echunk * 32 + lane;

    const float p0 = pos[e * 3 + 0];   // Y axis (faithful to reference)
    const float p1 = pos[e * 3 + 1];   // X axis
    const float p2 = pos[e * 3 + 2];   // Z axis

    // z terms (exact reference expressions)
    float pzf = (float)z - p2 + 28.0f;            // SPL_D/2 - ZPL/2
    float fz  = floorf(pzf);
    float dz  = pzf - fz;
    int   iz  = max(0, min((int)fz, SPL_D - 1));
    const int izoff = iz * SPL_H;

    // Base fractional parts / indices at y=0, x=0
    float py0 = (0.0f - p0) + 10.0f;              // SPL_H/2 - ROI/2
    float fy0 = floorf(py0);
    float dy  = py0 - fy0;
    int   iy0 = (int)fy0;

    float px0 = (0.0f - p1) + 10.0f;              // SPL_W/2 - ROI/2
    float fx0 = floorf(px0);
    float dx  = px0 - fx0;
    int   ix0 = (int)fx0;

    // Genericity: canonical translated grid + per-row/col floor pattern.
    bool ok = (iy0 == 9) && (ix0 == 9) && (iz == z + 27);
    #pragma unroll
    for (int q = 1; q < ROI; q++) {
        ok &= floorf(((float)q - p0) + 10.0f) == (float)(iy0 + q);
        ok &= floorf(((float)q - p1) + 10.0f) == (float)(ix0 + q);
    }

    const int  cnt    = (w < 16) ? 13 : 12;
    const int  pstart = (w < 16) ? w * 13 : 208 + (w - 16) * 12;
    const bool fast   = !__syncthreads_or(!ok);

    float dz2 = dz * dz, dz3 = dz2 * dz;
    float nsum = 0.0f;

    if (fast) {
        // ---- Stage 400 cells (100 KB) compactly: cell p -> sstage + p*64 ----
        {
            const float4* src4 = (const float4*)(coefs +
                ((((size_t)(z + 27) * SPL_H + 9) * SPL_W + 9) << 6));
            float4* dst4 = (float4*)sstage;
            #pragma unroll
            for (int k = 0; k < 7; k++) {
                int i = threadIdx.x + k * 1024;
                if (i < STAGE_F4) {
                    int y = i / 320;              // 20 cells * 16 f4 per row
                    int c = i - y * 320;
                    dst4[i] = src4[y * 640 + c];  // global row = 40 cells = 640 f4
                }
            }
        }

        // Packed per-thread weights: Wb[b][0] = (dy^b, dy^b*dx), Wb[b][1] = (dy^b*dx2, dy^b*dx3)
        float dx2 = dx * dx, dx3 = dx2 * dx;
        float dy2 = dy * dy, dy3 = dy2 * dy;
        const u64 q01 = fpack2(1.0f, dx);
        const u64 q23 = fpack2(dx2, dx3);
        u64 Wb[4][2];
        Wb[0][0] = q01;              Wb[0][1] = q23;
        u64 yd1 = fpack2(dy,  dy );  Wb[1][0] = fmul2(q01, yd1); Wb[1][1] = fmul2(q23, yd1);
        u64 yd2 = fpack2(dy2, dy2);  Wb[2][0] = fmul2(q01, yd2); Wb[2][1] = fmul2(q23, yd2);
        u64 yd3 = fpack2(dy3, dy3);  Wb[3][0] = fmul2(q01, yd3); Wb[3][1] = fmul2(q23, yd3);
        __syncthreads();

        #pragma unroll
        for (int i = 0; i < 13; i++) {
            if (i < cnt) {
                const int p = pstart + i;
                const ulonglong2* cp = (const ulonglong2*)(sstage + (p << 6));

                u64 acc0 = 0ULL, acc1 = 0ULL, acc2 = 0ULL, acc3 = 0ULL;
                #pragma unroll
                for (int bq = 0; bq < 4; bq++) {
                    ulonglong2 v0 = cp[0 * 4 + bq];   // a=0, b=bq
                    ulonglong2 v1 = cp[1 * 4 + bq];   // a=1
                    ulonglong2 v2 = cp[2 * 4 + bq];   // a=2
                    ulonglong2 v3 = cp[3 * 4 + bq];   // a=3
                    acc0 = ffma2(v0.x, Wb[bq][0], acc0);
                    acc1 = ffma2(v1.x, Wb[bq][0], acc1);
                    acc2 = ffma2(v2.x, Wb[bq][0], acc2);
                    acc3 = ffma2(v3.x, Wb[bq][0], acc3);
                    acc0 = ffma2(v0.y, Wb[bq][1], acc0);
                    acc1 = ffma2(v1.y, Wb[bq][1], acc1);
                    acc2 = ffma2(v2.y, Wb[bq][1], acc2);
                    acc3 = ffma2(v3.y, Wb[bq][1], acc3);
                }
                float s0 = fhadd2(acc0);
                float s1 = fhadd2(acc1);
                float s2 = fhadd2(acc2);
                float s3 = fhadd2(acc3);
                float v  = fmaf(s3, dz3, fmaf(s2, dz2, fmaf(s1, dz, s0)));

                sval[p * TPITCH + lane] = v;
                nsum += v;
            }
        }
    } else {
        // ---------------- EXACT FALLBACK (bit-faithful per pixel) -----------
        #pragma unroll 2
        for (int i = 0; i < 13; i++) {
            if (i < cnt) {
                const int p = pstart + i;
                const int y = p / 20;
                const int x = p - y * 20;

                float pyf = (float)y - p0 + 10.0f;
                float fy  = floorf(pyf);
                float dyy = pyf - fy;
                int   iy  = max(0, min((int)fy, SPL_H - 1));

                float pxf = (float)x - p1 + 10.0f;
                float fx  = floorf(pxf);
                float dxx = pxf - fx;
                int   ix  = max(0, min((int)fx, SPL_W - 1));

                float dxx2 = dxx * dxx, dxx3 = dxx2 * dxx;
                float dyy2 = dyy * dyy, dyy3 = dyy2 * dyy;

                const float4* cp = (const float4*)(coefs +
                    (((size_t)(izoff + iy) * SPL_W + ix) << 6));

                float s[4];
                #pragma unroll
                for (int a = 0; a < 4; a++) {
                    float4 c0 = cp[a * 4 + 0];
                    float4 c1 = cp[a * 4 + 1];
                    float4 c2 = cp[a * 4 + 2];
                    float4 c3 = cp[a * 4 + 3];
                    float t0 = fmaf(c0.w, dxx3, fmaf(c0.z, dxx2, fmaf(c0.y, dxx, c0.x)));
                    float t1 = fmaf(c1.w, dxx3, fmaf(c1.z, dxx2, fmaf(c1.y, dxx, c1.x)));
                    float t2 = fmaf(c2.w, dxx3, fmaf(c2.z, dxx2, fmaf(c2.y, dxx, c2.x)));
                    float t3 = fmaf(c3.w, dxx3, fmaf(c3.z, dxx2, fmaf(c3.y, dxx, c3.x)));
                    s[a] = fmaf(t3, dyy3, fmaf(t2, dyy2, fmaf(t1, dyy, t0)));
                }
                float v = fmaf(s[3], dz3, fmaf(s[2], dz2, fmaf(s[1], dz, s[0])));

                sval[p * TPITCH + lane] = v;
                nsum += v;
            }
        }
    }

    // Per-emitter plane sums
    ssum[w][lane] = nsum;
    __syncthreads();

    // Warp w handles emitter w: transposed read + butterfly reduce
    float t = ssum[lane][w];
    #pragma unroll
    for (int off = 16; off > 0; off >>= 1)
        t += __shfl_xor_sync(0xffffffffu, t, off);

    const int   eo  = echunk * 32 + w;
    const float sc  = inten[eo * ZPL + z] / t;
    const float bgv = bg[eo * ZPL + z];
    float* op = out + ((size_t)eo * ZPL + z) * NPX;

    #pragma unroll
    for (int m = 0; m < 13; m++) {
        int pp = m * 32 + lane;
        if (pp < NPX) op[pp] = fmaf(sval[pp * TPITCH + w], sc, bgv);
    }
}

extern "C" void kernel_launch(void* const* d_in, const int* in_sizes, int n_in,
                              void* d_out, int out_size)
{
    const float* pos   = (const float*)d_in[0];
    const float* inten = (const float*)d_in[1];
    const float* bg    = (const float*)d_in[2];
    const float* coefs = (const float*)d_in[3];

    const int smem = (25600 + NPX * TPITCH) * sizeof(float);   // ~154 KB dynamic
    cudaFuncSetAttribute(psf_fused, cudaFuncAttributeMaxDynamicSharedMemorySize, smem);
    psf_fused<<<128, 1024, smem>>>(pos, inten, bg, coefs, (float*)d_out);
}

// round 10
// speedup vs baseline: 1.7041x; 1.1317x over previous
#include <cuda_runtime.h>

#define N_EMIT 512
#define ZPL    8
#define ROI    20
#define NPX    400
#define SPL_D  64
#define SPL_H  40
#define SPL_W  40
#define TPITCH 33
#define STAGE_F4 6400            // 400 cells * 16 float4

typedef unsigned long long u64;

__device__ __forceinline__ u64 ffma2(u64 a, u64 b, u64 c) {
    u64 d;
    asm("fma.rn.f32x2 %0, %1, %2, %3;" : "=l"(d) : "l"(a), "l"(b), "l"(c));
    return d;
}
__device__ __forceinline__ u64 fmul2(u64 a, u64 b) {
    u64 d;
    asm("mul.rn.f32x2 %0, %1, %2;" : "=l"(d) : "l"(a), "l"(b));
    return d;
}
__device__ __forceinline__ u64 fpack2(float lo, float hi) {
    u64 d;
    asm("mov.b64 %0, {%1, %2};" : "=l"(d) : "f"(lo), "f"(hi));
    return d;
}
__device__ __forceinline__ float fhadd2(u64 a) {
    float lo, hi;
    asm("mov.b64 {%0, %1}, %2;" : "=f"(lo), "=f"(hi) : "l"(a));
    return lo + hi;
}

// One block = (echunk of 32 emitters) x (one z plane). 512 threads = 16 warps.
// lane = emitter; warp w owns pixels [w*25, w*25+25), processed pairwise for ILP.
__global__ __launch_bounds__(512, 1) void psf_fused(
    const float* __restrict__ pos,
    const float* __restrict__ inten,
    const float* __restrict__ bg,
    const float* __restrict__ coefs,
    float* __restrict__ out)
{
    extern __shared__ float dyn[];
    float* sstage = dyn;                  // 25600 floats (400 cells x 64)
    float* sval   = dyn + 25600;          // NPX * TPITCH
    __shared__ float ssum[16][TPITCH];

    const int echunk = blockIdx.x & 15;
    const int z      = blockIdx.x >> 4;
    const int w      = threadIdx.x >> 5;
    const int lane   = threadIdx.x & 31;
    const int e      = echunk * 32 + lane;

    const float p0 = pos[e * 3 + 0];   // Y axis (faithful to reference)
    const float p1 = pos[e * 3 + 1];   // X axis
    const float p2 = pos[e * 3 + 2];   // Z axis

    // z terms (exact reference expressions)
    float pzf = (float)z - p2 + 28.0f;            // SPL_D/2 - ZPL/2
    float fz  = floorf(pzf);
    float dz  = pzf - fz;
    int   iz  = max(0, min((int)fz, SPL_D - 1));
    const int izoff = iz * SPL_H;

    // Base fractional parts / indices at y=0, x=0
    float py0 = (0.0f - p0) + 10.0f;              // SPL_H/2 - ROI/2
    float fy0 = floorf(py0);
    float dy  = py0 - fy0;
    int   iy0 = (int)fy0;

    float px0 = (0.0f - p1) + 10.0f;              // SPL_W/2 - ROI/2
    float fx0 = floorf(px0);
    float dx  = px0 - fx0;
    int   ix0 = (int)fx0;

    // Genericity: canonical translated grid + per-row/col floor pattern.
    bool ok = (iy0 == 9) && (ix0 == 9) && (iz == z + 27);
    #pragma unroll
    for (int q = 1; q < ROI; q++) {
        ok &= floorf(((float)q - p0) + 10.0f) == (float)(iy0 + q);
        ok &= floorf(((float)q - p1) + 10.0f) == (float)(ix0 + q);
    }

    const bool fast = !__syncthreads_or(!ok);

    float dz2 = dz * dz, dz3 = dz2 * dz;
    float nsum = 0.0f;
    const int pstart = w * 25;

    if (fast) {
        // Packed per-thread weights: Wb[b][0]=(dy^b, dy^b*dx), Wb[b][1]=(dy^b*dx2, dy^b*dx3)
        float dx2 = dx * dx, dx3 = dx2 * dx;
        float dy2 = dy * dy, dy3 = dy2 * dy;
        const u64 q01 = fpack2(1.0f, dx);
        const u64 q23 = fpack2(dx2, dx3);
        u64 Wb[4][2];
        Wb[0][0] = q01;              Wb[0][1] = q23;
        u64 yd1 = fpack2(dy,  dy );  Wb[1][0] = fmul2(q01, yd1); Wb[1][1] = fmul2(q23, yd1);
        u64 yd2 = fpack2(dy2, dy2);  Wb[2][0] = fmul2(q01, yd2); Wb[2][1] = fmul2(q23, yd2);
        u64 yd3 = fpack2(dy3, dy3);  Wb[3][0] = fmul2(q01, yd3); Wb[3][1] = fmul2(q23, yd3);
        const u64 dzp  = fpack2(dz,  dz );
        const u64 dz2p = fpack2(dz2, dz2);
        const u64 dz3p = fpack2(dz3, dz3);

        // ---- Stage 400 cells (100 KB) compactly: cell p -> sstage + p*64 ----
        {
            const float4* src4 = (const float4*)(coefs +
                ((((size_t)(z + 27) * SPL_H + 9) * SPL_W + 9) << 6));
            float4* dst4 = (float4*)sstage;
            #pragma unroll
            for (int k = 0; k < 13; k++) {
                int i = threadIdx.x + k * 512;
                if (i < STAGE_F4) {
                    int y = i / 320;              // 20 cells * 16 f4 per row
                    int c = i - y * 320;
                    dst4[i] = src4[y * 640 + c];  // global row = 40 cells = 640 f4
                }
            }
        }
        __syncthreads();

        const ulonglong2* sb = (const ulonglong2*)sstage;   // 16 per cell

        // 12 pixel-pairs + 1 leftover; two independent accumulator sets for ILP.
        #pragma unroll 2
        for (int pr = 0; pr < 12; pr++) {
            const int pA = pstart + pr * 2;
            const int pB = pA + 1;
            const ulonglong2* cpA = sb + (pA << 4);
            const ulonglong2* cpB = sb + (pB << 4);

            u64 aA0 = 0, aA1 = 0, aA2 = 0, aA3 = 0;
            u64 aB0 = 0, aB1 = 0, aB2 = 0, aB3 = 0;
            #pragma unroll
            for (int bq = 0; bq < 4; bq++) {
                ulonglong2 A0 = cpA[ 0 + bq];
                ulonglong2 A1 = cpA[ 4 + bq];
                ulonglong2 A2 = cpA[ 8 + bq];
                ulonglong2 A3 = cpA[12 + bq];
                ulonglong2 B0 = cpB[ 0 + bq];
                ulonglong2 B1 = cpB[ 4 + bq];
                ulonglong2 B2 = cpB[ 8 + bq];
                ulonglong2 B3 = cpB[12 + bq];
                aA0 = ffma2(A0.x, Wb[bq][0], aA0);
                aA1 = ffma2(A1.x, Wb[bq][0], aA1);
                aA2 = ffma2(A2.x, Wb[bq][0], aA2);
                aA3 = ffma2(A3.x, Wb[bq][0], aA3);
                aB0 = ffma2(B0.x, Wb[bq][0], aB0);
                aB1 = ffma2(B1.x, Wb[bq][0], aB1);
                aB2 = ffma2(B2.x, Wb[bq][0], aB2);
                aB3 = ffma2(B3.x, Wb[bq][0], aB3);
                aA0 = ffma2(A0.y, Wb[bq][1], aA0);
                aA1 = ffma2(A1.y, Wb[bq][1], aA1);
                aA2 = ffma2(A2.y, Wb[bq][1], aA2);
                aA3 = ffma2(A3.y, Wb[bq][1], aA3);
                aB0 = ffma2(B0.y, Wb[bq][1], aB0);
                aB1 = ffma2(B1.y, Wb[bq][1], aB1);
                aB2 = ffma2(B2.y, Wb[bq][1], aB2);
                aB3 = ffma2(B3.y, Wb[bq][1], aB3);
            }
            // packed z-combine, single horizontal add at the end
            u64 mA = ffma2(aA1, dzp, aA0);
            u64 mB = ffma2(aB1, dzp, aB0);
            mA = ffma2(aA2, dz2p, mA);
            mB = ffma2(aB2, dz2p, mB);
            mA = ffma2(aA3, dz3p, mA);
            mB = ffma2(aB3, dz3p, mB);
            float vA = fhadd2(mA);
            float vB = fhadd2(mB);

            sval[pA * TPITCH + lane] = vA;
            sval[pB * TPITCH + lane] = vB;
            nsum += vA + vB;
        }
        {   // leftover pixel (pstart + 24)
            const int p = pstart + 24;
            const ulonglong2* cp = sb + (p << 4);
            u64 a0 = 0, a1 = 0, a2 = 0, a3 = 0;
            #pragma unroll
            for (int bq = 0; bq < 4; bq++) {
                ulonglong2 v0 = cp[ 0 + bq];
                ulonglong2 v1 = cp[ 4 + bq];
                ulonglong2 v2 = cp[ 8 + bq];
                ulonglong2 v3 = cp[12 + bq];
                a0 = ffma2(v0.x, Wb[bq][0], a0);
                a1 = ffma2(v1.x, Wb[bq][0], a1);
                a2 = ffma2(v2.x, Wb[bq][0], a2);
                a3 = ffma2(v3.x, Wb[bq][0], a3);
                a0 = ffma2(v0.y, Wb[bq][1], a0);
                a1 = ffma2(v1.y, Wb[bq][1], a1);
                a2 = ffma2(v2.y, Wb[bq][1], a2);
                a3 = ffma2(v3.y, Wb[bq][1], a3);
            }
            u64 m = ffma2(a1, dzp, a0);
            m = ffma2(a2, dz2p, m);
            m = ffma2(a3, dz3p, m);
            float v = fhadd2(m);
            sval[p * TPITCH + lane] = v;
            nsum += v;
        }
    } else {
        // ---------------- EXACT FALLBACK (bit-faithful per pixel) -----------
        for (int i = 0; i < 25; i++) {
            const int p = pstart + i;
            const int y = p / 20;
            const int x = p - y * 20;

            float pyf = (float)y - p0 + 10.0f;
            float fy  = floorf(pyf);
            float dyy = pyf - fy;
            int   iy  = max(0, min((int)fy, SPL_H - 1));

            float pxf = (float)x - p1 + 10.0f;
            float fx  = floorf(pxf);
            float dxx = pxf - fx;
            int   ix  = max(0, min((int)fx, SPL_W - 1));

            float dxx2 = dxx * dxx, dxx3 = dxx2 * dxx;
            float dyy2 = dyy * dyy, dyy3 = dyy2 * dyy;

            const float4* cp = (const float4*)(coefs +
                (((size_t)(izoff + iy) * SPL_W + ix) << 6));

            float s[4];
            #pragma unroll
            for (int a = 0; a < 4; a++) {
                float4 c0 = cp[a * 4 + 0];
                float4 c1 = cp[a * 4 + 1];
                float4 c2 = cp[a * 4 + 2];
                float4 c3 = cp[a * 4 + 3];
                float t0 = fmaf(c0.w, dxx3, fmaf(c0.z, dxx2, fmaf(c0.y, dxx, c0.x)));
                float t1 = fmaf(c1.w, dxx3, fmaf(c1.z, dxx2, fmaf(c1.y, dxx, c1.x)));
                float t2 = fmaf(c2.w, dxx3, fmaf(c2.z, dxx2, fmaf(c2.y, dxx, c2.x)));
                float t3 = fmaf(c3.w, dxx3, fmaf(c3.z, dxx2, fmaf(c3.y, dxx, c3.x)));
                s[a] = fmaf(t3, dyy3, fmaf(t2, dyy2, fmaf(t1, dyy, t0)));
            }
            float v = fmaf(s[3], dz3, fmaf(s[2], dz2, fmaf(s[1], dz, s[0])));

            sval[p * TPITCH + lane] = v;
            nsum += v;
        }
    }

    // Per-emitter plane sums
    ssum[w][lane] = nsum;
    __syncthreads();

    // Each warp reduces its two emitters (2w, 2w+1): half-warps read transposed.
    const int el = 2 * w + (lane >> 4);
    float t = ssum[lane & 15][el];
    t += __shfl_xor_sync(0xffffffffu, t, 8);
    t += __shfl_xor_sync(0xffffffffu, t, 4);
    t += __shfl_xor_sync(0xffffffffu, t, 2);
    t += __shfl_xor_sync(0xffffffffu, t, 1);
    const float tot0 = __shfl_sync(0xffffffffu, t, 0);
    const float tot1 = __shfl_sync(0xffffffffu, t, 16);

    #pragma unroll
    for (int q = 0; q < 2; q++) {
        const int   elq = 2 * w + q;
        const int   eo  = echunk * 32 + elq;
        const float sc  = inten[eo * ZPL + z] / (q ? tot1 : tot0);
        const float bgv = bg[eo * ZPL + z];
        float* op = out + ((size_t)eo * ZPL + z) * NPX;
        #pragma unroll
        for (int m = 0; m < 13; m++) {
            int pp = m * 32 + lane;
            if (pp < NPX) op[pp] = fmaf(sval[pp * TPITCH + elq], sc, bgv);
        }
    }
}

extern "C" void kernel_launch(void* const* d_in, const int* in_sizes, int n_in,
                              void* d_out, int out_size)
{
    const float* pos   = (const float*)d_in[0];
    const float* inten = (const float*)d_in[1];
    const float* bg    = (const float*)d_in[2];
    const float* coefs = (const float*)d_in[3];

    const int smem = (25600 + NPX * TPITCH) * sizeof(float);   // ~154 KB dynamic
    cudaFuncSetAttribute(psf_fused, cudaFuncAttributeMaxDynamicSharedMemorySize, smem);
    psf_fused<<<128, 512, smem>>>(pos, inten, bg, coefs, (float*)d_out);
}